// round 11
// baseline (speedup 1.0000x reference)
#include <cuda_runtime.h>
#include <cstdint>
#include <cstddef>

// ============================================================================
// Llama4 MoE Router on sm_103 — two kernels:
//  K1 gemm+topk: logits = hs @ gate_w^T (tf32 mma.sync, cp.async 4-stage,
//       ks-level fragment double buffering). Fused epilogue: logits to gmem
//       from fragments + smem; per-token top-3; safe tokens finalized,
//       near-ties appended to a device worklist.
//  K2 refine: 1 block per flagged token; exact fp64 dots, 256-thread parallel
//       per expert; overwrites weights/indices.
// Output (float32): [weights 32768*2][indices 32768*2][logits 32768*64]
// ============================================================================

#define TOKENS   32768
#define KDIM     4096
#define NEXP     64
#define BM       128
#define BK       32
#define NSTAGES  4
#define KITERS   (KDIM / BK)            // 128
#define THREADS  256
#define EPS      6e-3f
#define RGRID    1024

#define A_BYTES     (BM * BK * 4)       // 16384
#define B_BYTES     (NEXP * BK * 4)     // 8192
#define STAGE_BYTES (A_BYTES + B_BYTES) // 24576
#define SMEM_TOTAL  (NSTAGES * STAGE_BYTES)  // 98304
#define LG_STRIDE   68                  // padded logits row (floats)

// Refine worklist (device globals — no allocation).
__device__ int      d_count;
__device__ int      d_list[TOKENS];
__device__ unsigned d_mask0[TOKENS];
__device__ unsigned d_mask1[TOKENS];

__device__ __forceinline__ uint32_t smem_u32(const void* p) {
    uint32_t a;
    asm("{ .reg .u64 t; cvta.to.shared.u64 t, %1; cvt.u32.u64 %0, t; }" : "=r"(a) : "l"(p));
    return a;
}

__device__ __forceinline__ void cp16(uint32_t s, const void* g) {
    asm volatile("cp.async.cg.shared.global [%0], [%1], 16;" :: "r"(s), "l"(g) : "memory");
}

__device__ __forceinline__ void ldsm4(uint32_t& r0, uint32_t& r1, uint32_t& r2, uint32_t& r3,
                                      uint32_t addr) {
    asm volatile("ldmatrix.sync.aligned.m8n8.x4.shared.b16 {%0,%1,%2,%3}, [%4];"
                 : "=r"(r0), "=r"(r1), "=r"(r2), "=r"(r3) : "r"(addr));
}

__device__ __forceinline__ uint32_t rna_tf32(uint32_t x) {
    uint32_t r;
    asm("cvt.rna.tf32.f32 %0, %1;" : "=r"(r) : "f"(__uint_as_float(x)));
    return r;
}

__device__ __forceinline__ void mma8(float c[4], const uint32_t a[4], uint32_t b0, uint32_t b1) {
    asm volatile(
        "mma.sync.aligned.m16n8k8.row.col.f32.tf32.tf32.f32 "
        "{%0,%1,%2,%3}, {%4,%5,%6,%7}, {%8,%9}, {%0,%1,%2,%3};"
        : "+f"(c[0]), "+f"(c[1]), "+f"(c[2]), "+f"(c[3])
        : "r"(a[0]), "r"(a[1]), "r"(a[2]), "r"(a[3]), "r"(b0), "r"(b1));
}

__device__ __forceinline__ void load_stage(const float* __restrict__ hs,
                                           const float* __restrict__ gw,
                                           int m0, int kc, uint32_t sbase, int s, int tid) {
    const uint32_t ab = sbase + s * STAGE_BYTES;
    const uint32_t bb = ab + A_BYTES;
    #pragma unroll
    for (int j = 0; j < 4; j++) {
        int c  = tid + j * 256;
        int r  = c >> 3;
        int ch = c & 7;
        cp16(ab + r * 128 + ((ch ^ (r & 7)) << 4),
             hs + (size_t)(m0 + r) * KDIM + kc + ch * 4);
    }
    #pragma unroll
    for (int j = 0; j < 2; j++) {
        int c  = tid + j * 256;
        int e  = c >> 3;
        int ch = c & 7;
        cp16(bb + e * 128 + ((ch ^ (e & 7)) << 4),
             gw + (size_t)e * KDIM + kc + ch * 4);
    }
}

__global__ __launch_bounds__(THREADS, 1)
void gemm_kernel(const float* __restrict__ hs, const float* __restrict__ gw,
                 float* __restrict__ out) {
    // Reset worklist counter. Executes at t~0 of wave 1; earliest append is
    // after a full mainloop (~60+ us), so no race; deterministic per launch.
    if (blockIdx.x == 0 && threadIdx.x == 0) d_count = 0;

    extern __shared__ char smem[];
    const uint32_t sb = smem_u32(smem);
    const int tid  = threadIdx.x;
    const int wid  = tid >> 5;
    const int lane = tid & 31;
    const int m0   = blockIdx.x * BM;
    const int wm   = wid >> 1;
    const int wn   = wid & 1;
    const int lmat = lane >> 3;
    const int l8   = lane & 7;

    float c[2][4][4];
    #pragma unroll
    for (int mt = 0; mt < 2; mt++)
        #pragma unroll
        for (int nt = 0; nt < 4; nt++)
            #pragma unroll
            for (int q = 0; q < 4; q++) c[mt][nt][q] = 0.0f;

    #pragma unroll
    for (int j = 0; j < NSTAGES - 1; j++) {
        load_stage(hs, gw, m0, j * BK, sb, j, tid);
        asm volatile("cp.async.commit_group;" ::: "memory");
    }

    uint32_t af[2][2][4], bf[2][2][4];

    for (int i = 0; i < KITERS; i++) {
        asm volatile("cp.async.wait_group %0;" :: "n"(NSTAGES - 2) : "memory");
        __syncthreads();

        const uint32_t ab = sb + (i % NSTAGES) * STAGE_BYTES;
        const uint32_t bb = ab + A_BYTES;

        {
            const int ck = 0;
            #pragma unroll
            for (int mt = 0; mt < 2; mt++) {
                int r  = wm * 32 + mt * 16 + l8 + ((lmat & 1) << 3);
                int cc = ck + (lmat >> 1);
                ldsm4(af[0][mt][0], af[0][mt][1], af[0][mt][2], af[0][mt][3],
                      ab + r * 128 + ((cc ^ (r & 7)) << 4));
            }
            #pragma unroll
            for (int p = 0; p < 2; p++) {
                int r  = wn * 32 + p * 16 + l8 + ((lmat >> 1) << 3);
                int cc = ck + (lmat & 1);
                ldsm4(bf[0][p][0], bf[0][p][1], bf[0][p][2], bf[0][p][3],
                      bb + r * 128 + ((cc ^ (r & 7)) << 4));
            }
            #pragma unroll
            for (int mt = 0; mt < 2; mt++)
                #pragma unroll
                for (int q = 0; q < 4; q++) af[0][mt][q] = rna_tf32(af[0][mt][q]);
            #pragma unroll
            for (int p = 0; p < 2; p++)
                #pragma unroll
                for (int q = 0; q < 4; q++) bf[0][p][q] = rna_tf32(bf[0][p][q]);
        }

        #pragma unroll
        for (int ks = 0; ks < 4; ks++) {
            const int cur = ks & 1;
            const int nxt = cur ^ 1;

            if (ks < 3) {
                const int ck = (ks + 1) * 2;
                #pragma unroll
                for (int mt = 0; mt < 2; mt++) {
                    int r  = wm * 32 + mt * 16 + l8 + ((lmat & 1) << 3);
                    int cc = ck + (lmat >> 1);
                    ldsm4(af[nxt][mt][0], af[nxt][mt][1], af[nxt][mt][2], af[nxt][mt][3],
                          ab + r * 128 + ((cc ^ (r & 7)) << 4));
                }
                #pragma unroll
                for (int p = 0; p < 2; p++) {
                    int r  = wn * 32 + p * 16 + l8 + ((lmat >> 1) << 3);
                    int cc = ck + (lmat & 1);
                    ldsm4(bf[nxt][p][0], bf[nxt][p][1], bf[nxt][p][2], bf[nxt][p][3],
                          bb + r * 128 + ((cc ^ (r & 7)) << 4));
                }
            }

            #pragma unroll
            for (int mt = 0; mt < 2; mt++)
                #pragma unroll
                for (int nt = 0; nt < 4; nt++)
                    mma8(c[mt][nt], af[cur][mt], bf[cur][nt >> 1][(nt & 1) * 2],
                                                 bf[cur][nt >> 1][(nt & 1) * 2 + 1]);

            if (ks < 3) {
                #pragma unroll
                for (int mt = 0; mt < 2; mt++)
                    #pragma unroll
                    for (int q = 0; q < 4; q++) af[nxt][mt][q] = rna_tf32(af[nxt][mt][q]);
                #pragma unroll
                for (int p = 0; p < 2; p++)
                    #pragma unroll
                    for (int q = 0; q < 4; q++) bf[nxt][p][q] = rna_tf32(bf[nxt][p][q]);
            }
        }

        const int kn = i + NSTAGES - 1;
        if (kn < KITERS) load_stage(hs, gw, m0, kn * BK, sb, kn % NSTAGES, tid);
        asm volatile("cp.async.commit_group;" ::: "memory");
    }

    asm volatile("cp.async.wait_group 0;" ::: "memory");
    __syncthreads();   // smem stages dead; reuse for logits buffer

    // ---- Fused epilogue ----------------------------------------------------
    float* lgs = reinterpret_cast<float*>(smem);            // [128][68]
    float* lg_out = out + 4 * TOKENS;
    const int g = lane >> 2, q = lane & 3;
    #pragma unroll
    for (int mt = 0; mt < 2; mt++) {
        const int r0 = wm * 32 + mt * 16 + g;
        #pragma unroll
        for (int nt = 0; nt < 4; nt++) {
            const int col = wn * 32 + nt * 8 + 2 * q;
            lgs[r0 * LG_STRIDE + col]           = c[mt][nt][0];
            lgs[r0 * LG_STRIDE + col + 1]       = c[mt][nt][1];
            lgs[(r0 + 8) * LG_STRIDE + col]     = c[mt][nt][2];
            lgs[(r0 + 8) * LG_STRIDE + col + 1] = c[mt][nt][3];
            *reinterpret_cast<float2*>(lg_out + (size_t)(m0 + r0) * NEXP + col) =
                make_float2(c[mt][nt][0], c[mt][nt][1]);
            *reinterpret_cast<float2*>(lg_out + (size_t)(m0 + r0 + 8) * NEXP + col) =
                make_float2(c[mt][nt][2], c[mt][nt][3]);
        }
    }
    __syncthreads();

    if (tid < BM) {
        const int t = m0 + tid;
        float m1 = -1e30f, m2 = -1e30f, m3 = -1e30f;
        int i1 = 0, i2 = 0;
        #pragma unroll
        for (int j = 0; j < 16; j++) {
            float4 v = *reinterpret_cast<float4*>(&lgs[tid * LG_STRIDE + 4 * j]);
            float vv[4] = {v.x, v.y, v.z, v.w};
            #pragma unroll
            for (int u = 0; u < 4; u++) {
                int idx = 4 * j + u;
                if (vv[u] > m1)      { m3 = m2; m2 = m1; i2 = i1; m1 = vv[u]; i1 = idx; }
                else if (vv[u] > m2) { m3 = m2; m2 = vv[u]; i2 = idx; }
                else if (vv[u] > m3) { m3 = vv[u]; }
            }
        }
        if ((m1 - m2 >= EPS) && (m2 - m3 >= EPS)) {
            const float e   = __expf(m2 - m1);
            const float inv = 1.0f / (1.0f + e);
            *reinterpret_cast<float2*>(out + 2 * t) = make_float2(inv, e * inv);
            *reinterpret_cast<float2*>(out + 2 * TOKENS + 2 * t) =
                make_float2((float)i1, (float)i2);
        } else {
            // Near-tie: build candidate masks (bit e>>1 of mask[e&1]) and enqueue.
            const float thr = m2 - EPS;
            unsigned mk0 = 0, mk1 = 0;
            #pragma unroll
            for (int e = 0; e < NEXP; e++) {
                if (lgs[tid * LG_STRIDE + e] >= thr) {
                    if (e & 1) mk1 |= 1u << (e >> 1);
                    else       mk0 |= 1u << (e >> 1);
                }
            }
            const int slot = atomicAdd(&d_count, 1);
            d_list[slot]  = t;
            d_mask0[slot] = mk0;
            d_mask1[slot] = mk1;
        }
    }
}

// ============================================================================
// K2: one block per flagged token; per-expert exact fp64 dot with 256-thread
// parallelism (4 float4/thread — short chains, no spills), smem reduction.
// ============================================================================
__global__ __launch_bounds__(256, 4)
void refine_kernel(const float* __restrict__ hs, const float* __restrict__ gw,
                   float* __restrict__ out) {
    __shared__ double sred[8];
    __shared__ double sb[2];
    __shared__ int    sj[2];

    const int tid  = threadIdx.x;
    const int lane = tid & 31;
    const int wid  = tid >> 5;
    const int n    = d_count;

    for (int i = blockIdx.x; i < n; i += RGRID) {
        const int t = d_list[i];
        const unsigned mask0 = d_mask0[i];
        const unsigned mask1 = d_mask1[i];
        if (tid == 0) { sb[0] = -1e300; sb[1] = -1e300; sj[0] = 0; sj[1] = 0; }
        __syncthreads();

        const float4* ha = reinterpret_cast<const float4*>(hs + (size_t)t * KDIM);

        for (int e = 0; e < NEXP; e++) {
            const unsigned mm = (e & 1) ? mask1 : mask0;
            if (!((mm >> (e >> 1)) & 1u)) continue;

            const float4* ga = reinterpret_cast<const float4*>(gw + (size_t)e * KDIM);
            double acc[4];
            #pragma unroll
            for (int j = 0; j < 4; j++) {
                const int k = tid + j * 256;             // 1024 float4 total
                const float4 x = ha[k];
                const float4 y = ga[k];
                acc[j] = (double)x.x * y.x + (double)x.y * y.y
                       + (double)x.z * y.z + (double)x.w * y.w;
            }
            double a = (acc[0] + acc[1]) + (acc[2] + acc[3]);
            #pragma unroll
            for (int o = 16; o; o >>= 1) a += __shfl_down_sync(0xffffffffu, a, o);
            if (lane == 0) sred[wid] = a;
            __syncthreads();
            if (tid == 0) {
                double v = sred[0];
                #pragma unroll
                for (int w = 1; w < 8; w++) v += sred[w];
                if (v > sb[0])      { sb[1] = sb[0]; sj[1] = sj[0]; sb[0] = v; sj[0] = e; }
                else if (v > sb[1]) { sb[1] = v; sj[1] = e; }
            }
            __syncthreads();
        }

        if (tid == 0) {
            const float e   = __expf((float)(sb[1] - sb[0]));
            const float inv = 1.0f / (1.0f + e);
            *reinterpret_cast<float2*>(out + 2 * t) = make_float2(inv, e * inv);
            *reinterpret_cast<float2*>(out + 2 * TOKENS + 2 * t) =
                make_float2((float)sj[0], (float)sj[1]);
        }
        __syncthreads();
    }
}

extern "C" void kernel_launch(void* const* d_in, const int* in_sizes, int n_in,
                              void* d_out, int out_size) {
    (void)in_sizes; (void)n_in; (void)out_size;
    const float* hs = (const float*)d_in[0];   // [32768, 4096]
    const float* gw = (const float*)d_in[1];   // [64, 4096]
    float* out = (float*)d_out;

    cudaFuncSetAttribute(gemm_kernel,
                         cudaFuncAttributeMaxDynamicSharedMemorySize, SMEM_TOTAL);
    gemm_kernel<<<TOKENS / BM, THREADS, SMEM_TOTAL>>>(hs, gw, out);
    refine_kernel<<<RGRID, 256>>>(hs, gw, out);
}

// round 12
// speedup vs baseline: 1.0137x; 1.0137x over previous
#include <cuda_runtime.h>
#include <cstdint>
#include <cstddef>

// ============================================================================
// Llama4 MoE Router on sm_103 — three kernels (R10 structure):
//  K1 gemm:   logits = hs @ gate_w^T (tf32 mma.sync, cp.async 4-stage,
//             ks-level fragment double buffering), 2 CTAs/SM (single wave).
//  K2 topk:   per-token (1 warp) top-3; safe tokens finalized, near-ties
//             appended to a device worklist.
//  K3 refine: 1 block per flagged token; candidate experts processed in
//             PARALLEL across warps; exact fp64 dots; overwrites outputs.
// Output (float32): [weights 32768*2][indices 32768*2][logits 32768*64]
// ============================================================================

#define TOKENS   32768
#define KDIM     4096
#define NEXP     64
#define BM       128
#define BK       32
#define NSTAGES  4
#define KITERS   (KDIM / BK)            // 128
#define THREADS  256
#define EPS      6e-3f
#define RGRID    1024

#define A_BYTES     (BM * BK * 4)       // 16384
#define B_BYTES     (NEXP * BK * 4)     // 8192
#define STAGE_BYTES (A_BYTES + B_BYTES) // 24576
#define SMEM_TOTAL  (NSTAGES * STAGE_BYTES)  // 98304 -> 2 CTAs/SM (196 KB)

// Refine worklist (device globals — no allocation).
__device__ int      d_count;
__device__ int      d_list[TOKENS];
__device__ unsigned d_mask0[TOKENS];
__device__ unsigned d_mask1[TOKENS];

__device__ __forceinline__ uint32_t smem_u32(const void* p) {
    uint32_t a;
    asm("{ .reg .u64 t; cvta.to.shared.u64 t, %1; cvt.u32.u64 %0, t; }" : "=r"(a) : "l"(p));
    return a;
}

__device__ __forceinline__ void cp16(uint32_t s, const void* g) {
    asm volatile("cp.async.cg.shared.global [%0], [%1], 16;" :: "r"(s), "l"(g) : "memory");
}

__device__ __forceinline__ void ldsm4(uint32_t& r0, uint32_t& r1, uint32_t& r2, uint32_t& r3,
                                      uint32_t addr) {
    asm volatile("ldmatrix.sync.aligned.m8n8.x4.shared.b16 {%0,%1,%2,%3}, [%4];"
                 : "=r"(r0), "=r"(r1), "=r"(r2), "=r"(r3) : "r"(addr));
}

__device__ __forceinline__ uint32_t rna_tf32(uint32_t x) {
    uint32_t r;
    asm("cvt.rna.tf32.f32 %0, %1;" : "=r"(r) : "f"(__uint_as_float(x)));
    return r;
}

__device__ __forceinline__ void mma8(float c[4], const uint32_t a[4], uint32_t b0, uint32_t b1) {
    asm volatile(
        "mma.sync.aligned.m16n8k8.row.col.f32.tf32.tf32.f32 "
        "{%0,%1,%2,%3}, {%4,%5,%6,%7}, {%8,%9}, {%0,%1,%2,%3};"
        : "+f"(c[0]), "+f"(c[1]), "+f"(c[2]), "+f"(c[3])
        : "r"(a[0]), "r"(a[1]), "r"(a[2]), "r"(a[3]), "r"(b0), "r"(b1));
}

__device__ __forceinline__ void load_stage(const float* __restrict__ hs,
                                           const float* __restrict__ gw,
                                           int m0, int kc, uint32_t sbase, int s, int tid) {
    const uint32_t ab = sbase + s * STAGE_BYTES;
    const uint32_t bb = ab + A_BYTES;
    #pragma unroll
    for (int j = 0; j < 4; j++) {
        int c  = tid + j * 256;
        int r  = c >> 3;
        int ch = c & 7;
        cp16(ab + r * 128 + ((ch ^ (r & 7)) << 4),
             hs + (size_t)(m0 + r) * KDIM + kc + ch * 4);
    }
    #pragma unroll
    for (int j = 0; j < 2; j++) {
        int c  = tid + j * 256;
        int e  = c >> 3;
        int ch = c & 7;
        cp16(bb + e * 128 + ((ch ^ (e & 7)) << 4),
             gw + (size_t)e * KDIM + kc + ch * 4);
    }
}

__global__ __launch_bounds__(THREADS, 2)
void gemm_kernel(const float* __restrict__ hs, const float* __restrict__ gw,
                 float* __restrict__ out) {
    if (blockIdx.x == 0 && threadIdx.x == 0) d_count = 0;   // reset worklist

    extern __shared__ char smem[];
    const uint32_t sb = smem_u32(smem);
    const int tid  = threadIdx.x;
    const int wid  = tid >> 5;
    const int lane = tid & 31;
    const int m0   = blockIdx.x * BM;
    const int wm   = wid >> 1;
    const int wn   = wid & 1;
    const int lmat = lane >> 3;
    const int l8   = lane & 7;

    float c[2][4][4];
    #pragma unroll
    for (int mt = 0; mt < 2; mt++)
        #pragma unroll
        for (int nt = 0; nt < 4; nt++)
            #pragma unroll
            for (int q = 0; q < 4; q++) c[mt][nt][q] = 0.0f;

    #pragma unroll
    for (int j = 0; j < NSTAGES - 1; j++) {
        load_stage(hs, gw, m0, j * BK, sb, j, tid);
        asm volatile("cp.async.commit_group;" ::: "memory");
    }

    uint32_t af[2][2][4], bf[2][2][4];

    for (int i = 0; i < KITERS; i++) {
        asm volatile("cp.async.wait_group %0;" :: "n"(NSTAGES - 2) : "memory");
        __syncthreads();

        const uint32_t ab = sb + (i % NSTAGES) * STAGE_BYTES;
        const uint32_t bb = ab + A_BYTES;

        {
            const int ck = 0;
            #pragma unroll
            for (int mt = 0; mt < 2; mt++) {
                int r  = wm * 32 + mt * 16 + l8 + ((lmat & 1) << 3);
                int cc = ck + (lmat >> 1);
                ldsm4(af[0][mt][0], af[0][mt][1], af[0][mt][2], af[0][mt][3],
                      ab + r * 128 + ((cc ^ (r & 7)) << 4));
            }
            #pragma unroll
            for (int p = 0; p < 2; p++) {
                int r  = wn * 32 + p * 16 + l8 + ((lmat >> 1) << 3);
                int cc = ck + (lmat & 1);
                ldsm4(bf[0][p][0], bf[0][p][1], bf[0][p][2], bf[0][p][3],
                      bb + r * 128 + ((cc ^ (r & 7)) << 4));
            }
            #pragma unroll
            for (int mt = 0; mt < 2; mt++)
                #pragma unroll
                for (int q = 0; q < 4; q++) af[0][mt][q] = rna_tf32(af[0][mt][q]);
            #pragma unroll
            for (int p = 0; p < 2; p++)
                #pragma unroll
                for (int q = 0; q < 4; q++) bf[0][p][q] = rna_tf32(bf[0][p][q]);
        }

        #pragma unroll
        for (int ks = 0; ks < 4; ks++) {
            const int cur = ks & 1;
            const int nxt = cur ^ 1;

            if (ks < 3) {
                const int ck = (ks + 1) * 2;
                #pragma unroll
                for (int mt = 0; mt < 2; mt++) {
                    int r  = wm * 32 + mt * 16 + l8 + ((lmat & 1) << 3);
                    int cc = ck + (lmat >> 1);
                    ldsm4(af[nxt][mt][0], af[nxt][mt][1], af[nxt][mt][2], af[nxt][mt][3],
                          ab + r * 128 + ((cc ^ (r & 7)) << 4));
                }
                #pragma unroll
                for (int p = 0; p < 2; p++) {
                    int r  = wn * 32 + p * 16 + l8 + ((lmat >> 1) << 3);
                    int cc = ck + (lmat & 1);
                    ldsm4(bf[nxt][p][0], bf[nxt][p][1], bf[nxt][p][2], bf[nxt][p][3],
                          bb + r * 128 + ((cc ^ (r & 7)) << 4));
                }
            }

            #pragma unroll
            for (int mt = 0; mt < 2; mt++)
                #pragma unroll
                for (int nt = 0; nt < 4; nt++)
                    mma8(c[mt][nt], af[cur][mt], bf[cur][nt >> 1][(nt & 1) * 2],
                                                 bf[cur][nt >> 1][(nt & 1) * 2 + 1]);

            if (ks < 3) {
                #pragma unroll
                for (int mt = 0; mt < 2; mt++)
                    #pragma unroll
                    for (int q = 0; q < 4; q++) af[nxt][mt][q] = rna_tf32(af[nxt][mt][q]);
                #pragma unroll
                for (int p = 0; p < 2; p++)
                    #pragma unroll
                    for (int q = 0; q < 4; q++) bf[nxt][p][q] = rna_tf32(bf[nxt][p][q]);
            }
        }

        const int kn = i + NSTAGES - 1;
        if (kn < KITERS) load_stage(hs, gw, m0, kn * BK, sb, kn % NSTAGES, tid);
        asm volatile("cp.async.commit_group;" ::: "memory");
    }

    float* lg_out = out + 4 * TOKENS;
    const int g = lane >> 2, q = lane & 3;
    #pragma unroll
    for (int mt = 0; mt < 2; mt++) {
        const int r0 = wm * 32 + mt * 16 + g;
        #pragma unroll
        for (int nt = 0; nt < 4; nt++) {
            const int col = wn * 32 + nt * 8 + 2 * q;
            *reinterpret_cast<float2*>(lg_out + (size_t)(m0 + r0) * NEXP + col) =
                make_float2(c[mt][nt][0], c[mt][nt][1]);
            *reinterpret_cast<float2*>(lg_out + (size_t)(m0 + r0 + 8) * NEXP + col) =
                make_float2(c[mt][nt][2], c[mt][nt][3]);
        }
    }
}

// ============================================================================
// K2: one warp per token — top-3 select; safe tokens finalized, near-ties
// appended to the device worklist (no heavy math here).
// ============================================================================
__global__ __launch_bounds__(256, 4)
void topk_kernel(float* __restrict__ out) {
    const int t    = (blockIdx.x * 256 + threadIdx.x) >> 5;
    const int lane = threadIdx.x & 31;
    const float* lg = out + 4 * TOKENS + (size_t)t * NEXP;

    const float2 v2 = *reinterpret_cast<const float2*>(lg + 2 * lane);
    float vals[2] = {v2.x, v2.y};
    int   idxs[2] = {2 * lane, 2 * lane + 1};
    bool  used[2] = {false, false};

    float m[3]; int mi[3];
    #pragma unroll
    for (int r = 0; r < 3; r++) {
        float bv = -1e30f; int bi = 9999;
        #pragma unroll
        for (int u = 0; u < 2; u++)
            if (!used[u] && (vals[u] > bv || (vals[u] == bv && idxs[u] < bi))) {
                bv = vals[u]; bi = idxs[u];
            }
        #pragma unroll
        for (int o = 16; o; o >>= 1) {
            float ov = __shfl_xor_sync(0xffffffffu, bv, o);
            int   oi = __shfl_xor_sync(0xffffffffu, bi, o);
            if (ov > bv || (ov == bv && oi < bi)) { bv = ov; bi = oi; }
        }
        m[r] = bv; mi[r] = bi;
        #pragma unroll
        for (int u = 0; u < 2; u++)
            if (idxs[u] == bi) used[u] = true;
    }

    if ((m[0] - m[1] >= EPS) && (m[1] - m[2] >= EPS)) {
        if (lane == 0) {
            const float e   = __expf(m[1] - m[0]);
            const float inv = 1.0f / (1.0f + e);
            *reinterpret_cast<float2*>(out + 2 * t) = make_float2(inv, e * inv);
            *reinterpret_cast<float2*>(out + 2 * TOKENS + 2 * t) =
                make_float2((float)mi[0], (float)mi[1]);
        }
        return;
    }

    const float thr = m[1] - EPS;
    const unsigned mask0 = __ballot_sync(0xffffffffu, vals[0] >= thr);
    const unsigned mask1 = __ballot_sync(0xffffffffu, vals[1] >= thr);
    if (lane == 0) {
        const int slot = atomicAdd(&d_count, 1);
        d_list[slot]  = t;
        d_mask0[slot] = mask0;
        d_mask1[slot] = mask1;
    }
}

// ============================================================================
// K3: one block per flagged token; candidate experts distributed over the 8
// warps (parallel fp64 dots, unroll-4 to keep MLP without spills); thread 0
// picks top-2 from smem values.
// ============================================================================
__global__ __launch_bounds__(256, 4)
void refine_kernel(const float* __restrict__ hs, const float* __restrict__ gw,
                   float* __restrict__ out) {
    __shared__ int    s_cand[NEXP];
    __shared__ int    s_ncand;
    __shared__ double s_val[NEXP];

    const int tid  = threadIdx.x;
    const int lane = tid & 31;
    const int wid  = tid >> 5;
    const int n    = d_count;

    for (int i = blockIdx.x; i < n; i += RGRID) {
        const int t = d_list[i];
        if (tid == 0) {
            const unsigned mk0 = d_mask0[i];
            const unsigned mk1 = d_mask1[i];
            int nc = 0;
            #pragma unroll
            for (int e = 0; e < NEXP; e++) {
                const unsigned mm = (e & 1) ? mk1 : mk0;
                if ((mm >> (e >> 1)) & 1u) s_cand[nc++] = e;
            }
            s_ncand = nc;
        }
        __syncthreads();

        const int nc = s_ncand;
        const float4* ha = reinterpret_cast<const float4*>(hs + (size_t)t * KDIM);

        for (int ci = wid; ci < nc; ci += 8) {
            const int e = s_cand[ci];
            const float4* ga = reinterpret_cast<const float4*>(gw + (size_t)e * KDIM);
            double acc[4] = {0.0, 0.0, 0.0, 0.0};
            #pragma unroll 4
            for (int j = 0; j < 32; j++) {        // 32 x 32-lane strides = 1024 float4
                const int k = lane + j * 32;
                const float4 x = ha[k];
                const float4 y = ga[k];
                acc[j & 3] += (double)x.x * y.x + (double)x.y * y.y
                            + (double)x.z * y.z + (double)x.w * y.w;
            }
            double a = (acc[0] + acc[1]) + (acc[2] + acc[3]);
            #pragma unroll
            for (int o = 16; o; o >>= 1) a += __shfl_down_sync(0xffffffffu, a, o);
            if (lane == 0) s_val[ci] = a;
        }
        __syncthreads();

        if (tid == 0) {
            double b1 = -1e300, b2 = -1e300;
            int j1 = 0, j2 = 0;
            for (int ci = 0; ci < nc; ci++) {      // ascending expert id = tie-break
                const double v = s_val[ci];
                const int    e = s_cand[ci];
                if (v > b1)      { b2 = b1; j2 = j1; b1 = v; j1 = e; }
                else if (v > b2) { b2 = v; j2 = e; }
            }
            const float ex  = __expf((float)(b2 - b1));
            const float inv = 1.0f / (1.0f + ex);
            *reinterpret_cast<float2*>(out + 2 * t) = make_float2(inv, ex * inv);
            *reinterpret_cast<float2*>(out + 2 * TOKENS + 2 * t) =
                make_float2((float)j1, (float)j2);
        }
        __syncthreads();
    }
}

extern "C" void kernel_launch(void* const* d_in, const int* in_sizes, int n_in,
                              void* d_out, int out_size) {
    (void)in_sizes; (void)n_in; (void)out_size;
    const float* hs = (const float*)d_in[0];   // [32768, 4096]
    const float* gw = (const float*)d_in[1];   // [64, 4096]
    float* out = (float*)d_out;

    cudaFuncSetAttribute(gemm_kernel,
                         cudaFuncAttributeMaxDynamicSharedMemorySize, SMEM_TOTAL);
    gemm_kernel<<<TOKENS / BM, THREADS, SMEM_TOTAL>>>(hs, gw, out);
    topk_kernel<<<TOKENS * 32 / 256, 256>>>(out);
    refine_kernel<<<RGRID, 256>>>(hs, gw, out);
}

// round 13
// speedup vs baseline: 1.5597x; 1.5386x over previous
#include <cuda_runtime.h>
#include <cstdint>
#include <cstddef>

// ============================================================================
// Llama4 MoE Router on sm_103 — three kernels:
//  K1 gemm:   logits = hs @ gate_w^T (tf32 mma.sync, cp.async 4-stage,
//             ks-level fragment double buffering). ~120 us, DRAM 57%.
//  K2 topk:   per-token (1 warp) top-3; safe tokens finalized, near-ties
//             appended to a device worklist.
//  K3 refine: 1 block per flagged token; candidate experts parallel across
//             warps; DOUBLE-FLOAT compensated fp32 dots (no fp64 pipe).
// Output (float32): [weights 32768*2][indices 32768*2][logits 32768*64]
// ============================================================================

#define TOKENS   32768
#define KDIM     4096
#define NEXP     64
#define BM       128
#define BK       32
#define NSTAGES  4
#define KITERS   (KDIM / BK)            // 128
#define THREADS  256
#define EPS      6e-3f
#define RGRID    1024

#define A_BYTES     (BM * BK * 4)       // 16384
#define B_BYTES     (NEXP * BK * 4)     // 8192
#define STAGE_BYTES (A_BYTES + B_BYTES) // 24576
#define SMEM_TOTAL  (NSTAGES * STAGE_BYTES)  // 98304 (2 CTAs/SM resident)

// Refine worklist (device globals — no allocation).
__device__ int      d_count;
__device__ int      d_list[TOKENS];
__device__ unsigned d_mask0[TOKENS];
__device__ unsigned d_mask1[TOKENS];

__device__ __forceinline__ uint32_t smem_u32(const void* p) {
    uint32_t a;
    asm("{ .reg .u64 t; cvta.to.shared.u64 t, %1; cvt.u32.u64 %0, t; }" : "=r"(a) : "l"(p));
    return a;
}

__device__ __forceinline__ void cp16(uint32_t s, const void* g) {
    asm volatile("cp.async.cg.shared.global [%0], [%1], 16;" :: "r"(s), "l"(g) : "memory");
}

__device__ __forceinline__ void ldsm4(uint32_t& r0, uint32_t& r1, uint32_t& r2, uint32_t& r3,
                                      uint32_t addr) {
    asm volatile("ldmatrix.sync.aligned.m8n8.x4.shared.b16 {%0,%1,%2,%3}, [%4];"
                 : "=r"(r0), "=r"(r1), "=r"(r2), "=r"(r3) : "r"(addr));
}

__device__ __forceinline__ uint32_t rna_tf32(uint32_t x) {
    uint32_t r;
    asm("cvt.rna.tf32.f32 %0, %1;" : "=r"(r) : "f"(__uint_as_float(x)));
    return r;
}

__device__ __forceinline__ void mma8(float c[4], const uint32_t a[4], uint32_t b0, uint32_t b1) {
    asm volatile(
        "mma.sync.aligned.m16n8k8.row.col.f32.tf32.tf32.f32 "
        "{%0,%1,%2,%3}, {%4,%5,%6,%7}, {%8,%9}, {%0,%1,%2,%3};"
        : "+f"(c[0]), "+f"(c[1]), "+f"(c[2]), "+f"(c[3])
        : "r"(a[0]), "r"(a[1]), "r"(a[2]), "r"(a[3]), "r"(b0), "r"(b1));
}

// Error-free product + Knuth TwoSum accumulate: (s, c) += x*y exactly
// (up to rounding of the c-stream, ~2^-48 relative on the total).
__device__ __forceinline__ void dacc(float& s, float& c, float x, float y) {
    const float p = __fmul_rn(x, y);
    const float e = fmaf(x, y, -p);     // exact product error
    const float t = __fadd_rn(s, p);
    const float z = __fsub_rn(t, s);
    c = __fadd_rn(c, __fadd_rn(__fadd_rn(__fsub_rn(s, __fsub_rn(t, z)),
                                         __fsub_rn(p, z)), e));
    s = t;
}

__device__ __forceinline__ void load_stage(const float* __restrict__ hs,
                                           const float* __restrict__ gw,
                                           int m0, int kc, uint32_t sbase, int s, int tid) {
    const uint32_t ab = sbase + s * STAGE_BYTES;
    const uint32_t bb = ab + A_BYTES;
    #pragma unroll
    for (int j = 0; j < 4; j++) {
        int c  = tid + j * 256;
        int r  = c >> 3;
        int ch = c & 7;
        cp16(ab + r * 128 + ((ch ^ (r & 7)) << 4),
             hs + (size_t)(m0 + r) * KDIM + kc + ch * 4);
    }
    #pragma unroll
    for (int j = 0; j < 2; j++) {
        int c  = tid + j * 256;
        int e  = c >> 3;
        int ch = c & 7;
        cp16(bb + e * 128 + ((ch ^ (e & 7)) << 4),
             gw + (size_t)e * KDIM + kc + ch * 4);
    }
}

__global__ __launch_bounds__(THREADS, 2)
void gemm_kernel(const float* __restrict__ hs, const float* __restrict__ gw,
                 float* __restrict__ out) {
    if (blockIdx.x == 0 && threadIdx.x == 0) d_count = 0;   // reset worklist

    extern __shared__ char smem[];
    const uint32_t sb = smem_u32(smem);
    const int tid  = threadIdx.x;
    const int wid  = tid >> 5;
    const int lane = tid & 31;
    const int m0   = blockIdx.x * BM;
    const int wm   = wid >> 1;
    const int wn   = wid & 1;
    const int lmat = lane >> 3;
    const int l8   = lane & 7;

    float c[2][4][4];
    #pragma unroll
    for (int mt = 0; mt < 2; mt++)
        #pragma unroll
        for (int nt = 0; nt < 4; nt++)
            #pragma unroll
            for (int q = 0; q < 4; q++) c[mt][nt][q] = 0.0f;

    #pragma unroll
    for (int j = 0; j < NSTAGES - 1; j++) {
        load_stage(hs, gw, m0, j * BK, sb, j, tid);
        asm volatile("cp.async.commit_group;" ::: "memory");
    }

    uint32_t af[2][2][4], bf[2][2][4];

    for (int i = 0; i < KITERS; i++) {
        asm volatile("cp.async.wait_group %0;" :: "n"(NSTAGES - 2) : "memory");
        __syncthreads();

        const uint32_t ab = sb + (i % NSTAGES) * STAGE_BYTES;
        const uint32_t bb = ab + A_BYTES;

        {
            const int ck = 0;
            #pragma unroll
            for (int mt = 0; mt < 2; mt++) {
                int r  = wm * 32 + mt * 16 + l8 + ((lmat & 1) << 3);
                int cc = ck + (lmat >> 1);
                ldsm4(af[0][mt][0], af[0][mt][1], af[0][mt][2], af[0][mt][3],
                      ab + r * 128 + ((cc ^ (r & 7)) << 4));
            }
            #pragma unroll
            for (int p = 0; p < 2; p++) {
                int r  = wn * 32 + p * 16 + l8 + ((lmat >> 1) << 3);
                int cc = ck + (lmat & 1);
                ldsm4(bf[0][p][0], bf[0][p][1], bf[0][p][2], bf[0][p][3],
                      bb + r * 128 + ((cc ^ (r & 7)) << 4));
            }
            #pragma unroll
            for (int mt = 0; mt < 2; mt++)
                #pragma unroll
                for (int q = 0; q < 4; q++) af[0][mt][q] = rna_tf32(af[0][mt][q]);
            #pragma unroll
            for (int p = 0; p < 2; p++)
                #pragma unroll
                for (int q = 0; q < 4; q++) bf[0][p][q] = rna_tf32(bf[0][p][q]);
        }

        #pragma unroll
        for (int ks = 0; ks < 4; ks++) {
            const int cur = ks & 1;
            const int nxt = cur ^ 1;

            if (ks < 3) {
                const int ck = (ks + 1) * 2;
                #pragma unroll
                for (int mt = 0; mt < 2; mt++) {
                    int r  = wm * 32 + mt * 16 + l8 + ((lmat & 1) << 3);
                    int cc = ck + (lmat >> 1);
                    ldsm4(af[nxt][mt][0], af[nxt][mt][1], af[nxt][mt][2], af[nxt][mt][3],
                          ab + r * 128 + ((cc ^ (r & 7)) << 4));
                }
                #pragma unroll
                for (int p = 0; p < 2; p++) {
                    int r  = wn * 32 + p * 16 + l8 + ((lmat >> 1) << 3);
                    int cc = ck + (lmat & 1);
                    ldsm4(bf[nxt][p][0], bf[nxt][p][1], bf[nxt][p][2], bf[nxt][p][3],
                          bb + r * 128 + ((cc ^ (r & 7)) << 4));
                }
            }

            #pragma unroll
            for (int mt = 0; mt < 2; mt++)
                #pragma unroll
                for (int nt = 0; nt < 4; nt++)
                    mma8(c[mt][nt], af[cur][mt], bf[cur][nt >> 1][(nt & 1) * 2],
                                                 bf[cur][nt >> 1][(nt & 1) * 2 + 1]);

            if (ks < 3) {
                #pragma unroll
                for (int mt = 0; mt < 2; mt++)
                    #pragma unroll
                    for (int q = 0; q < 4; q++) af[nxt][mt][q] = rna_tf32(af[nxt][mt][q]);
                #pragma unroll
                for (int p = 0; p < 2; p++)
                    #pragma unroll
                    for (int q = 0; q < 4; q++) bf[nxt][p][q] = rna_tf32(bf[nxt][p][q]);
            }
        }

        const int kn = i + NSTAGES - 1;
        if (kn < KITERS) load_stage(hs, gw, m0, kn * BK, sb, kn % NSTAGES, tid);
        asm volatile("cp.async.commit_group;" ::: "memory");
    }

    float* lg_out = out + 4 * TOKENS;
    const int g = lane >> 2, q = lane & 3;
    #pragma unroll
    for (int mt = 0; mt < 2; mt++) {
        const int r0 = wm * 32 + mt * 16 + g;
        #pragma unroll
        for (int nt = 0; nt < 4; nt++) {
            const int col = wn * 32 + nt * 8 + 2 * q;
            *reinterpret_cast<float2*>(lg_out + (size_t)(m0 + r0) * NEXP + col) =
                make_float2(c[mt][nt][0], c[mt][nt][1]);
            *reinterpret_cast<float2*>(lg_out + (size_t)(m0 + r0 + 8) * NEXP + col) =
                make_float2(c[mt][nt][2], c[mt][nt][3]);
        }
    }
}

// ============================================================================
// K2: one warp per token — top-3 select; safe tokens finalized, near-ties
// appended to the device worklist.
// ============================================================================
__global__ __launch_bounds__(256, 4)
void topk_kernel(float* __restrict__ out) {
    const int t    = (blockIdx.x * 256 + threadIdx.x) >> 5;
    const int lane = threadIdx.x & 31;
    const float* lg = out + 4 * TOKENS + (size_t)t * NEXP;

    const float2 v2 = *reinterpret_cast<const float2*>(lg + 2 * lane);
    float vals[2] = {v2.x, v2.y};
    int   idxs[2] = {2 * lane, 2 * lane + 1};
    bool  used[2] = {false, false};

    float m[3]; int mi[3];
    #pragma unroll
    for (int r = 0; r < 3; r++) {
        float bv = -1e30f; int bi = 9999;
        #pragma unroll
        for (int u = 0; u < 2; u++)
            if (!used[u] && (vals[u] > bv || (vals[u] == bv && idxs[u] < bi))) {
                bv = vals[u]; bi = idxs[u];
            }
        #pragma unroll
        for (int o = 16; o; o >>= 1) {
            float ov = __shfl_xor_sync(0xffffffffu, bv, o);
            int   oi = __shfl_xor_sync(0xffffffffu, bi, o);
            if (ov > bv || (ov == bv && oi < bi)) { bv = ov; bi = oi; }
        }
        m[r] = bv; mi[r] = bi;
        #pragma unroll
        for (int u = 0; u < 2; u++)
            if (idxs[u] == bi) used[u] = true;
    }

    if ((m[0] - m[1] >= EPS) && (m[1] - m[2] >= EPS)) {
        if (lane == 0) {
            const float e   = __expf(m[1] - m[0]);
            const float inv = 1.0f / (1.0f + e);
            *reinterpret_cast<float2*>(out + 2 * t) = make_float2(inv, e * inv);
            *reinterpret_cast<float2*>(out + 2 * TOKENS + 2 * t) =
                make_float2((float)mi[0], (float)mi[1]);
        }
        return;
    }

    const float thr = m[1] - EPS;
    const unsigned mask0 = __ballot_sync(0xffffffffu, vals[0] >= thr);
    const unsigned mask1 = __ballot_sync(0xffffffffu, vals[1] >= thr);
    if (lane == 0) {
        const int slot = atomicAdd(&d_count, 1);
        d_list[slot]  = t;
        d_mask0[slot] = mask0;
        d_mask1[slot] = mask1;
    }
}

// ============================================================================
// K3: one block per flagged token; candidate experts distributed over the 8
// warps; per-lane DOUBLE-FLOAT compensated fp32 accumulation (fp32 pipe only),
// final cross-lane reduction in fp64 (10 DADDs per expert — negligible).
// ============================================================================
__global__ __launch_bounds__(256, 4)
void refine_kernel(const float* __restrict__ hs, const float* __restrict__ gw,
                   float* __restrict__ out) {
    __shared__ int    s_cand[NEXP];
    __shared__ int    s_ncand;
    __shared__ double s_val[NEXP];

    const int tid  = threadIdx.x;
    const int lane = tid & 31;
    const int wid  = tid >> 5;
    const int n    = d_count;

    for (int i = blockIdx.x; i < n; i += RGRID) {
        const int t = d_list[i];
        if (tid == 0) {
            const unsigned mk0 = d_mask0[i];
            const unsigned mk1 = d_mask1[i];
            int nc = 0;
            #pragma unroll
            for (int e = 0; e < NEXP; e++) {
                const unsigned mm = (e & 1) ? mk1 : mk0;
                if ((mm >> (e >> 1)) & 1u) s_cand[nc++] = e;
            }
            s_ncand = nc;
        }
        __syncthreads();

        const int nc = s_ncand;
        const float4* ha = reinterpret_cast<const float4*>(hs + (size_t)t * KDIM);

        for (int ci = wid; ci < nc; ci += 8) {
            const int e = s_cand[ci];
            const float4* ga = reinterpret_cast<const float4*>(gw + (size_t)e * KDIM);
            float s0 = 0.f, c0 = 0.f, s1 = 0.f, c1 = 0.f;
            #pragma unroll 4
            for (int j = 0; j < 32; j++) {        // 32 x 32-lane strides = 1024 float4
                const int k = lane + j * 32;
                const float4 x = ha[k];
                const float4 y = ga[k];
                if (j & 1) {
                    dacc(s1, c1, x.x, y.x); dacc(s1, c1, x.y, y.y);
                    dacc(s1, c1, x.z, y.z); dacc(s1, c1, x.w, y.w);
                } else {
                    dacc(s0, c0, x.x, y.x); dacc(s0, c0, x.y, y.y);
                    dacc(s0, c0, x.z, y.z); dacc(s0, c0, x.w, y.w);
                }
            }
            double a = ((double)s0 + (double)s1) + ((double)c0 + (double)c1);
            #pragma unroll
            for (int o = 16; o; o >>= 1) a += __shfl_down_sync(0xffffffffu, a, o);
            if (lane == 0) s_val[ci] = a;
        }
        __syncthreads();

        if (tid == 0) {
            double b1 = -1e300, b2 = -1e300;
            int j1 = 0, j2 = 0;
            for (int ci = 0; ci < nc; ci++) {      // ascending expert id = tie-break
                const double v = s_val[ci];
                const int    e = s_cand[ci];
                if (v > b1)      { b2 = b1; j2 = j1; b1 = v; j1 = e; }
                else if (v > b2) { b2 = v; j2 = e; }
            }
            const float ex  = __expf((float)(b2 - b1));
            const float inv = 1.0f / (1.0f + ex);
            *reinterpret_cast<float2*>(out + 2 * t) = make_float2(inv, ex * inv);
            *reinterpret_cast<float2*>(out + 2 * TOKENS + 2 * t) =
                make_float2((float)j1, (float)j2);
        }
        __syncthreads();
    }
}

extern "C" void kernel_launch(void* const* d_in, const int* in_sizes, int n_in,
                              void* d_out, int out_size) {
    (void)in_sizes; (void)n_in; (void)out_size;
    const float* hs = (const float*)d_in[0];   // [32768, 4096]
    const float* gw = (const float*)d_in[1];   // [64, 4096]
    float* out = (float*)d_out;

    cudaFuncSetAttribute(gemm_kernel,
                         cudaFuncAttributeMaxDynamicSharedMemorySize, SMEM_TOTAL);
    gemm_kernel<<<TOKENS / BM, THREADS, SMEM_TOTAL>>>(hs, gw, out);
    topk_kernel<<<TOKENS * 32 / 256, 256>>>(out);
    refine_kernel<<<RGRID, 256>>>(hs, gw, out);
}